// round 8
// baseline (speedup 1.0000x reference)
#include <cuda_runtime.h>
#include <cuda_bf16.h>
#include <math.h>

#define BB 8
#define PP 2048
#define CC 21
#define CENTER_VAR 0.1f
#define SIZE_VAR 0.2f
#define GEPS 1e-8f

#define NTHR 256
#define NWARP (NTHR / 32)
#define ITEMS (PP / NTHR)        // 8 items per thread, CTA b handles batch b

// Global scratch for compacted boxes only. Validity is defined by counts that
// are recomputed in smem every run -> no cross-replay state, nothing to reset.
__device__ float4 g_boxA[BB][PP];
__device__ float4 g_boxT[BB][PP];
__device__ int    g_nA[BB];
__device__ int    g_nT[BB];

// Fast exp on the FMA pipe (no MUFU). x <= 0 expected; rel err ~1e-7.
__device__ __forceinline__ float fexp(float x) {
    float y = x * 1.44269504f;                 // log2(e)
    int   ni = __float2int_rn(y);
    float f  = y - (float)ni;                  // f in [-0.5, 0.5]
    float p  = 0.00133335581f;
    p = p * f + 0.00961812910f;
    p = p * f + 0.05550410866f;
    p = p * f + 0.24022650696f;
    p = p * f + 0.69314718056f;
    p = p * f + 1.0f;
    ni = max(ni, -126);
    float s = __int_as_float((unsigned)(ni + 127) << 23);
    return p * s;
}

__global__ void __launch_bounds__(NTHR, 1) __cluster_dims__(BB, 1, 1)
iou_loss_fused(const float* __restrict__ conf,
               const float* __restrict__ loc,
               const int*   __restrict__ tc,
               const float* __restrict__ tloc,
               const float* __restrict__ priors,
               float* __restrict__ out) {
    const int tid  = threadIdx.x;
    const int b    = blockIdx.x;        // one CTA per batch; single cluster of 8
    const int lane = tid & 31;
    const int wid  = tid >> 5;

    __shared__ float s_conf[NWARP][32 * CC];   // per-warp staging buffer
    __shared__ int   s_cT, s_cA;
    if (tid == 0) { s_cT = 0; s_cA = 0; }

    // ---- dtype probe (CTA-local). int64 LE {0,1} -> odd words all zero -----
    int w0 = (tid < 128) ? tc[2 * tid + 1] : 0;
    const bool is64 = (__syncthreads_or(w0) == 0);   // also covers s_cT/s_cA init

    // ---- Phase 1: classify + decode + CTA-local compaction -----------------
    #pragma unroll 1
    for (int i = 0; i < ITEMS; i++) {
        const int p   = i * NTHR + tid;          // 0..2047 within batch b
        const int idx = b * PP + p;

        // warp-coalesced conf staging: this warp's 32 rows -> smem
        {
            const float4* g4 = (const float4*)(conf + (size_t)(b * PP + i * NTHR + wid * 32) * CC);
            float4* s4 = (float4*)s_conf[wid];
            #pragma unroll
            for (int j = lane; j < (32 * CC) / 4; j += 32) s4[j] = g4[j];
        }
        __syncwarp();

        float4 pr = ((const float4*)priors)[p];
        float4 lt = ((const float4*)tloc)[idx];
        float4 ll = ((const float4*)loc)[idx];
        const int tv = is64 ? tc[2 * idx] : tc[idx];

        const float* cf = &s_conf[wid][lane * CC];
        float m = cf[0]; int mi = 0;
        #pragma unroll
        for (int c = 1; c < CC; c++) {
            float v = cf[c];
            if (v > m) { m = v; mi = c; }
        }
        float se = 0.f;
        #pragma unroll
        for (int c = 0; c < CC; c++) se += fexp(cf[c] - m);
        if (fabsf(se - 2.0f) < 1e-3f) {          // boundary guard: full precision
            se = 0.f;
            #pragma unroll
            for (int c = 0; c < CC; c++) se += expf(cf[c] - m);
        }

        const bool isT = (tv > 0);
        const bool isA = isT && (se < 2.0f) && (mi > 0);   // maxp = 1/se > 0.5

        if (isT) {
            float cx = pr.x + lt.x * CENTER_VAR * pr.z;
            float cy = pr.y + lt.y * CENTER_VAR * pr.w;
            float w  = pr.z * fexp(lt.z * SIZE_VAR);
            float h  = pr.w * fexp(lt.w * SIZE_VAR);
            float x0 = cx - 0.5f * w, y0 = cy - 0.5f * h;
            // warp-aggregated smem-counter slot
            unsigned mk = __ballot_sync(__activemask(), 1);
            (void)mk;
            int slot = atomicAdd(&s_cT, 1);
            g_boxT[b][slot] = make_float4(x0, y0, x0 + w, y0 + h);
        }
        if (isA) {
            float cx = pr.x + ll.x * CENTER_VAR * pr.z;
            float cy = pr.y + ll.y * CENTER_VAR * pr.w;
            float w  = pr.z * fexp(ll.z * SIZE_VAR);
            float h  = pr.w * fexp(ll.w * SIZE_VAR);
            float x0 = cx - 0.5f * w, y0 = cy - 0.5f * h;
            int slot = atomicAdd(&s_cA, 1);
            g_boxA[b][slot] = make_float4(x0, y0, x0 + w, y0 + h);
        }
        __syncwarp();                            // protect staging buffer reuse
    }

    // publish counts + ensure box writes visible cluster-wide
    __syncthreads();
    if (tid == 0) { g_nT[b] = s_cT; g_nA[b] = s_cA; __threadfence(); }

    // ---- HW cluster barrier (release/acquire, ~hundreds of cycles) ---------
    asm volatile("barrier.cluster.arrive.aligned;" ::: "memory");
    asm volatile("barrier.cluster.wait.aligned;"   ::: "memory");

    // ---- Tail: ALL CTAs compute redundantly (symmetric exit); CTA0 stores --
    __shared__ int   t_cT[BB];
    __shared__ int   t_nA[BB];
    __shared__ int   t_off[BB + 1];
    __shared__ float t_S[BB];
    if (tid < BB) {
        t_cT[tid] = g_nT[tid];
        t_nA[tid] = g_nA[tid];
        t_S[tid]  = 0.f;
    }
    __syncthreads();
    if (tid == 0) {
        int o = 0;
        #pragma unroll
        for (int q = 0; q < BB; q++) { t_off[q] = o; o += t_nA[q] * t_cT[q]; }
        t_off[BB] = o;
    }
    __syncthreads();
    const int total = t_off[BB];

    for (int k = tid; k < total; k += NTHR) {
        int bb = 0;
        #pragma unroll
        for (int q = 1; q < BB; q++) bb += (k >= t_off[q]);
        int lk = k - t_off[bb];
        int nt = t_cT[bb];
        int a  = lk / nt;
        int t  = lk - a * nt;

        float4 A = g_boxA[bb][a];
        float4 T = g_boxT[bb][t];
        float ix = fminf(A.z, T.z) - fmaxf(A.x, T.x);
        float iy = fminf(A.w, T.w) - fmaxf(A.y, T.y);
        float inter = fmaxf(ix, 0.f) * fmaxf(iy, 0.f);
        float areaA = (A.z - A.x) * (A.w - A.y);
        float areaT = (T.z - T.x) * (T.w - T.y);
        float uni = areaA + areaT - inter;
        float iou = __fdividef(inter, fmaxf(uni, GEPS));
        float ex = fmaxf(A.z, T.z) - fminf(A.x, T.x);
        float ey = fmaxf(A.w, T.w) - fminf(A.y, T.y);
        float enc = ex * ey;
        float g = iou - __fdividef(enc - uni, fmaxf(enc, GEPS));
        atomicAdd(&t_S[bb], g);
    }
    __syncthreads();

    if (tid < 32) {
        float term = 0.f, ntv = 0.f;
        if (tid < BB) {
            float nt = (float)t_cT[tid];
            float na = (float)t_nA[tid];
            bool bt = nt > 0.f, ba = na > 0.f;
            if (bt && ba)      term = nt - t_S[tid] / fmaxf(nt, 1.f);
            else if (bt != ba) term = 1.f;
            else               term = 0.f;
            ntv = nt;
        }
        #pragma unroll
        for (int o = 4; o > 0; o >>= 1) {
            term += __shfl_down_sync(0xffffffffu, term, o);
            ntv  += __shfl_down_sync(0xffffffffu, ntv, o);
        }
        if (tid == 0 && b == 0) out[0] = term / fmaxf(ntv, 1.f);
    }
}

extern "C" void kernel_launch(void* const* d_in, const int* in_sizes, int n_in,
                              void* d_out, int out_size) {
    const float* conf   = (const float*)d_in[0];
    const float* loc    = (const float*)d_in[1];
    const int*   tc     = (const int*)d_in[2];
    const float* tloc   = (const float*)d_in[3];
    const float* priors = (const float*)d_in[4];
    float* out = (float*)d_out;

    iou_loss_fused<<<BB, NTHR>>>(conf, loc, tc, tloc, priors, out);
}

// round 9
// speedup vs baseline: 1.0765x; 1.0765x over previous
#include <cuda_runtime.h>
#include <cuda_bf16.h>
#include <math.h>

#define BB 8
#define PP 2048
#define CC 21
#define CENTER_VAR 0.1f
#define SIZE_VAR 0.2f
#define GEPS 1e-8f

#define NBLK 64
#define NTHR 256
#define NWARP (NTHR / 32)
#define SEGS 8                       // blocks (segments) per batch
#define SEGN (PP / SEGS)             // 256 rows per segment

// Scratch: segment boxes + per-segment counts. Counts are OVERWRITTEN by every
// block every replay -> no cross-replay state, no reset, no reset/read race.
__device__ float4 g_boxA[BB][PP];
__device__ float4 g_boxT[BB][PP];
__device__ int    g_segA[NBLK];
__device__ int    g_segT[NBLK];
__device__ unsigned g_bar;           // monotonic ticket barrier (mask-based)

__device__ __forceinline__ float4 decode_box(float4 l, float4 pr) {
    float cx = pr.x + l.x * CENTER_VAR * pr.z;
    float cy = pr.y + l.y * CENTER_VAR * pr.w;
    float w  = pr.z * __expf(l.z * SIZE_VAR);
    float h  = pr.w * __expf(l.w * SIZE_VAR);
    float x0 = cx - 0.5f * w;
    float y0 = cy - 0.5f * h;
    return make_float4(x0, y0, x0 + w, y0 + h);
}

__global__ void __launch_bounds__(NTHR, 1)
iou_loss_fused(const float* __restrict__ conf,
               const float* __restrict__ loc,
               const int*   __restrict__ tc,
               const float* __restrict__ tloc,
               const float* __restrict__ priors,
               float* __restrict__ out) {
    const int tid  = threadIdx.x;
    const int bid  = blockIdx.x;
    const int lane = tid & 31;
    const int wid  = tid >> 5;
    const int b    = bid >> 3;          // batch of this block
    const int seg  = bid & 7;           // segment within batch
    const int p    = seg * SEGN + tid;  // row within batch
    const int idx  = b * PP + p;

    __shared__ float s_conf[NWARP][32 * CC];
    __shared__ int   s_cT, s_cA;
    if (tid == 0) { s_cT = 0; s_cA = 0; }

    // ---- Warp-coalesced conf staging --------------------------------------
    {
        const float4* g4 = (const float4*)(conf + (size_t)(b * PP + seg * SEGN + wid * 32) * CC);
        float4* s4 = (float4*)s_conf[wid];
        #pragma unroll
        for (int j = lane; j < (32 * CC) / 4; j += 32) s4[j] = g4[j];
    }

    float4 pr = ((const float4*)priors)[p];
    float4 lt = ((const float4*)tloc)[idx];
    float4 ll = ((const float4*)loc)[idx];

    // ---- dtype probe (block-local). int64 LE {0,1} -> odd words all zero ---
    int w0 = (tid < 128) ? tc[2 * tid + 1] : 0;
    const bool is64 = (__syncthreads_or(w0) == 0);  // orders staging + s_c init
    const int tv = is64 ? tc[2 * idx] : tc[idx];

    // ---- Classify + decode --------------------------------------------------
    float4 boxT = decode_box(lt, pr);
    float4 boxA = decode_box(ll, pr);

    const float* cf = &s_conf[wid][lane * CC];
    float m = cf[0]; int mi = 0;
    #pragma unroll
    for (int c = 1; c < CC; c++) {
        float v = cf[c];
        if (v > m) { m = v; mi = c; }
    }
    float se = 0.f;
    #pragma unroll
    for (int c = 0; c < CC; c++) se += __expf(cf[c] - m);
    if (fabsf(se - 2.0f) < 1e-3f) {     // threshold-boundary guard
        se = 0.f;
        #pragma unroll
        for (int c = 0; c < CC; c++) se += expf(cf[c] - m);
    }

    const bool isT = (tv > 0);
    const bool isA = isT && (se < 2.0f) && (mi > 0);    // maxp = 1/se > 0.5

    // ---- Warp-aggregated compaction into this block's PRIVATE segment ------
    unsigned mT = __ballot_sync(0xffffffffu, isT);
    if (mT) {
        int ldr = __ffs(mT) - 1, base;
        if (lane == ldr) base = atomicAdd(&s_cT, __popc(mT));
        base = __shfl_sync(0xffffffffu, base, ldr);
        if (isT) g_boxT[b][seg * SEGN + base + __popc(mT & ((1u << lane) - 1u))] = boxT;
    }
    unsigned mA = __ballot_sync(0xffffffffu, isA);
    if (mA) {
        int ldr = __ffs(mA) - 1, base;
        if (lane == ldr) base = atomicAdd(&s_cA, __popc(mA));
        base = __shfl_sync(0xffffffffu, base, ldr);
        if (isA) g_boxA[b][seg * SEGN + base + __popc(mA & ((1u << lane) - 1u))] = boxA;
    }
    __syncthreads();
    if (tid == 0) { g_segT[bid] = s_cT; g_segA[bid] = s_cA; }

    // ---- Single grid epoch: spin barrier (all blocks stay resident) --------
    __syncthreads();
    if (tid == 0) {
        __threadfence();                               // release boxes + counts
        unsigned t = atomicAdd(&g_bar, 1u);
        unsigned target = (t / NBLK + 1u) * NBLK;
        while (*((volatile unsigned*)&g_bar) < target) { __nanosleep(64); }
        __threadfence();                               // acquire
    }
    __syncthreads();

    // ---- Tail: every block computes redundantly (symmetric); b0 stores -----
    __shared__ int   sA[NBLK], sT[NBLK];      // per-segment counts
    __shared__ int   pA[NBLK], pT[NBLK];      // excl. prefix within batch
    __shared__ int   nA[BB], nT[BB];
    __shared__ float t_S[BB];
    if (tid < NBLK) { sA[tid] = g_segA[tid]; sT[tid] = g_segT[tid]; }
    if (tid < BB) t_S[tid] = 0.f;
    __syncthreads();
    if (tid < BB) {
        int oa = 0, ot = 0;
        #pragma unroll
        for (int j = 0; j < SEGS; j++) {
            pA[tid * SEGS + j] = oa; oa += sA[tid * SEGS + j];
            pT[tid * SEGS + j] = ot; ot += sT[tid * SEGS + j];
        }
        nA[tid] = oa; nT[tid] = ot;
    }
    __syncthreads();

    __shared__ int off[BB + 1];
    if (tid == 0) {
        int o = 0;
        #pragma unroll
        for (int q = 0; q < BB; q++) { off[q] = o; o += nA[q] * nT[q]; }
        off[BB] = o;
    }
    __syncthreads();
    const int total = off[BB];

    if (total > 0) {
        for (int k = tid; k < total; k += NTHR) {
            int bb = 0;
            #pragma unroll
            for (int q = 1; q < BB; q++) bb += (k >= off[q]);
            int lk = k - off[bb];
            int ntb = nT[bb];
            int a  = lk / ntb;
            int t  = lk - a * ntb;
            // map logical index -> segment-local (prefix sums nondecreasing)
            int ja = 0, jt = 0;
            #pragma unroll
            for (int q = 1; q < SEGS; q++) {
                ja += (a >= pA[bb * SEGS + q]);
                jt += (t >= pT[bb * SEGS + q]);
            }
            float4 A = g_boxA[bb][ja * SEGN + (a - pA[bb * SEGS + ja])];
            float4 T = g_boxT[bb][jt * SEGN + (t - pT[bb * SEGS + jt])];
            float ix = fminf(A.z, T.z) - fmaxf(A.x, T.x);
            float iy = fminf(A.w, T.w) - fmaxf(A.y, T.y);
            float inter = fmaxf(ix, 0.f) * fmaxf(iy, 0.f);
            float areaA = (A.z - A.x) * (A.w - A.y);
            float areaT = (T.z - T.x) * (T.w - T.y);
            float uni = areaA + areaT - inter;
            float iou = __fdividef(inter, fmaxf(uni, GEPS));
            float ex = fmaxf(A.z, T.z) - fminf(A.x, T.x);
            float ey = fmaxf(A.w, T.w) - fminf(A.y, T.y);
            float enc = ex * ey;
            float g = iou - __fdividef(enc - uni, fmaxf(enc, GEPS));
            atomicAdd(&t_S[bb], g);
        }
        __syncthreads();
    }

    if (tid < 32) {
        float term = 0.f, ntv = 0.f;
        if (tid < BB) {
            float nt = (float)nT[tid];
            float na = (float)nA[tid];
            bool bt = nt > 0.f, ba = na > 0.f;
            if (bt && ba)      term = nt - t_S[tid] / fmaxf(nt, 1.f);
            else if (bt != ba) term = 1.f;
            else               term = 0.f;
            ntv = nt;
        }
        #pragma unroll
        for (int o = 4; o > 0; o >>= 1) {
            term += __shfl_down_sync(0xffffffffu, term, o);
            ntv  += __shfl_down_sync(0xffffffffu, ntv, o);
        }
        if (tid == 0 && bid == 0) out[0] = term / fmaxf(ntv, 1.f);
    }
}

extern "C" void kernel_launch(void* const* d_in, const int* in_sizes, int n_in,
                              void* d_out, int out_size) {
    const float* conf   = (const float*)d_in[0];
    const float* loc    = (const float*)d_in[1];
    const int*   tc     = (const int*)d_in[2];
    const float* tloc   = (const float*)d_in[3];
    const float* priors = (const float*)d_in[4];
    float* out = (float*)d_out;

    iou_loss_fused<<<NBLK, NTHR>>>(conf, loc, tc, tloc, priors, out);
}